// round 4
// baseline (speedup 1.0000x reference)
#include <cuda_runtime.h>
#include <cstdint>

// ---------------------------------------------------------------------------
// PCQLinear: w_q = fakequant(weight, global min/max); out = x @ w_q^T + bias;
// per-cluster (K groups of B/K rows) min/max -> EMA range update -> fakequant.
// Output buffer: [B*OUT floats of out_q][K*2 floats of new_range].
// ---------------------------------------------------------------------------

#define BM 128
#define BN 128
#define BK 16
#define TM 8
#define TN 8
#define NTHREADS 256

#define FLT_BIG 3.402823466e38f

// Scratch (allocation-free: __device__ globals)
__device__ float g_wq[4096 * 4096];      // quantized weight
__device__ unsigned g_wmin_u, g_wmax_u;  // ordered-uint encoded fp32 min/max
__device__ float g_sw, g_zw;
__device__ unsigned g_cmin[64], g_cmax[64];
__device__ float g_s3[64], g_z3[64];

// Order-preserving float<->uint encoding so atomicMin/Max on unsigned works.
__device__ __forceinline__ unsigned f2ord(float f) {
    unsigned u = __float_as_uint(f);
    return (u & 0x80000000u) ? ~u : (u | 0x80000000u);
}
__device__ __forceinline__ float ord2f(unsigned u) {
    return __uint_as_float((u & 0x80000000u) ? (u & 0x7FFFFFFFu) : ~u);
}

// ---------------------------------------------------------------------------
__global__ void init_scratch_kernel() {
    int t = threadIdx.x;
    if (t == 0) { g_wmin_u = 0xFFFFFFFFu; g_wmax_u = 0u; }
    if (t < 64) { g_cmin[t] = 0xFFFFFFFFu; g_cmax[t] = 0u; }
}

// ---------------------------------------------------------------------------
__global__ void wminmax_kernel(const float* __restrict__ w, long n4) {
    float mn = FLT_BIG, mx = -FLT_BIG;
    long stride = (long)gridDim.x * blockDim.x;
    for (long i = (long)blockIdx.x * blockDim.x + threadIdx.x; i < n4; i += stride) {
        float4 v = ((const float4*)w)[i];
        mn = fminf(mn, fminf(fminf(v.x, v.y), fminf(v.z, v.w)));
        mx = fmaxf(mx, fmaxf(fmaxf(v.x, v.y), fmaxf(v.z, v.w)));
    }
    #pragma unroll
    for (int o = 16; o; o >>= 1) {
        mn = fminf(mn, __shfl_down_sync(0xFFFFFFFFu, mn, o));
        mx = fmaxf(mx, __shfl_down_sync(0xFFFFFFFFu, mx, o));
    }
    __shared__ float smn[8], smx[8];
    int lane = threadIdx.x & 31, wrp = threadIdx.x >> 5;
    if (!lane) { smn[wrp] = mn; smx[wrp] = mx; }
    __syncthreads();
    if (threadIdx.x == 0) {
        for (int i = 1; i < (int)(blockDim.x >> 5); i++) {
            mn = fminf(mn, smn[i]); mx = fmaxf(mx, smx[i]);
        }
        atomicMin(&g_wmin_u, f2ord(mn));
        atomicMax(&g_wmax_u, f2ord(mx));
    }
}

__global__ void wparams_kernel() {
    float mn = ord2f(g_wmin_u), mx = ord2f(g_wmax_u);
    float s = __fdiv_rn(mx - mn, 255.0f);
    g_sw = s;
    g_zw = -rintf(__fdiv_rn(mn, s));
}

__global__ void wquant_kernel(const float* __restrict__ w, long n4) {
    float s = g_sw, zp = g_zw;
    long stride = (long)gridDim.x * blockDim.x;
    for (long i = (long)blockIdx.x * blockDim.x + threadIdx.x; i < n4; i += stride) {
        float4 v = ((const float4*)w)[i];
        v.x = (fminf(fmaxf(rintf(__fdiv_rn(v.x, s) + zp), 0.0f), 255.0f) - zp) * s;
        v.y = (fminf(fmaxf(rintf(__fdiv_rn(v.y, s) + zp), 0.0f), 255.0f) - zp) * s;
        v.z = (fminf(fmaxf(rintf(__fdiv_rn(v.z, s) + zp), 0.0f), 255.0f) - zp) * s;
        v.w = (fminf(fmaxf(rintf(__fdiv_rn(v.w, s) + zp), 0.0f), 255.0f) - zp) * s;
        ((float4*)g_wq)[i] = v;
    }
}

// ---------------------------------------------------------------------------
// GEMM: out[M,N] = X[M,IN] * Wq[N,IN]^T + bias[N]; epilogue per-cluster min/max.
// 128x128 block tile, BK=16, 8x8 per thread, double-buffered smem.
// ---------------------------------------------------------------------------
__global__ __launch_bounds__(NTHREADS, 2)
void gemm_kernel(const float* __restrict__ X, const float* __restrict__ bias,
                 float* __restrict__ out, int IND, int ND, int nPerCluster) {
    __shared__ float As[2][BK][BM];
    __shared__ float Bs[2][BK][BN];

    const int tid = threadIdx.x;
    const int tx = tid & 15;        // 0..15 -> N
    const int ty = tid >> 4;        // 0..15 -> M
    const int m0 = blockIdx.y * BM;
    const int n0 = blockIdx.x * BN;

    const int lrow = tid >> 2;          // 0..63
    const int lk4  = (tid & 3) * 4;     // 0,4,8,12

    const float* Ap0 = X + (size_t)(m0 + lrow) * IND + lk4;
    const float* Ap1 = X + (size_t)(m0 + lrow + 64) * IND + lk4;
    const float* Bp0 = g_wq + (size_t)(n0 + lrow) * IND + lk4;
    const float* Bp1 = g_wq + (size_t)(n0 + lrow + 64) * IND + lk4;

    const int ntiles = IND / BK;

    float4 ra0, ra1, rb0, rb1;

    auto loadG = [&](int kt) {
        int off = kt * BK;
        ra0 = *(const float4*)(Ap0 + off);
        ra1 = *(const float4*)(Ap1 + off);
        rb0 = *(const float4*)(Bp0 + off);
        rb1 = *(const float4*)(Bp1 + off);
    };
    auto storeS = [&](float (*Asl)[BM], float (*Bsl)[BN]) {
        Asl[lk4 + 0][lrow] = ra0.x; Asl[lk4 + 1][lrow] = ra0.y;
        Asl[lk4 + 2][lrow] = ra0.z; Asl[lk4 + 3][lrow] = ra0.w;
        Asl[lk4 + 0][lrow + 64] = ra1.x; Asl[lk4 + 1][lrow + 64] = ra1.y;
        Asl[lk4 + 2][lrow + 64] = ra1.z; Asl[lk4 + 3][lrow + 64] = ra1.w;
        Bsl[lk4 + 0][lrow] = rb0.x; Bsl[lk4 + 1][lrow] = rb0.y;
        Bsl[lk4 + 2][lrow] = rb0.z; Bsl[lk4 + 3][lrow] = rb0.w;
        Bsl[lk4 + 0][lrow + 64] = rb1.x; Bsl[lk4 + 1][lrow + 64] = rb1.y;
        Bsl[lk4 + 2][lrow + 64] = rb1.z; Bsl[lk4 + 3][lrow + 64] = rb1.w;
    };

    float acc[TM][TN];
    #pragma unroll
    for (int i = 0; i < TM; i++)
        #pragma unroll
        for (int j = 0; j < TN; j++) acc[i][j] = 0.0f;

    auto compute = [&](const float (*Asl)[BM], const float (*Bsl)[BN]) {
        #pragma unroll
        for (int kk = 0; kk < BK; kk++) {
            float a[TM], b[TN];
            *(float4*)(a)     = *(const float4*)&Asl[kk][ty * TM];
            *(float4*)(a + 4) = *(const float4*)&Asl[kk][ty * TM + 4];
            *(float4*)(b)     = *(const float4*)&Bsl[kk][tx * TN];
            *(float4*)(b + 4) = *(const float4*)&Bsl[kk][tx * TN + 4];
            #pragma unroll
            for (int i = 0; i < TM; i++)
                #pragma unroll
                for (int j = 0; j < TN; j++)
                    acc[i][j] += a[i] * b[j];
        }
    };

    // Prologue: tile 0 -> buf 0
    loadG(0);
    storeS(As[0], Bs[0]);
    __syncthreads();

    // Main loop, 2 tiles per iteration (ntiles = IN/16 = 256, even)
    for (int kt = 0; kt < ntiles; kt += 2) {
        if (kt + 1 < ntiles) loadG(kt + 1);
        compute(As[0], Bs[0]);
        if (kt + 1 < ntiles) storeS(As[1], Bs[1]);
        __syncthreads();

        if (kt + 1 < ntiles) {
            if (kt + 2 < ntiles) loadG(kt + 2);
            compute(As[1], Bs[1]);
            if (kt + 2 < ntiles) storeS(As[0], Bs[0]);
            __syncthreads();
        }
    }

    // Epilogue: bias add, store, per-cluster min/max
    float bv[TN];
    *(float4*)(bv)     = *(const float4*)&bias[n0 + tx * TN];
    *(float4*)(bv + 4) = *(const float4*)&bias[n0 + tx * TN + 4];

    float lmin = FLT_BIG, lmax = -FLT_BIG;
    #pragma unroll
    for (int i = 0; i < TM; i++) {
        float v[TN];
        #pragma unroll
        for (int j = 0; j < TN; j++) {
            v[j] = acc[i][j] + bv[j];
            lmin = fminf(lmin, v[j]);
            lmax = fmaxf(lmax, v[j]);
        }
        float* orow = out + (size_t)(m0 + ty * TM + i) * ND + n0 + tx * TN;
        *(float4*)(orow)     = *(const float4*)(v);
        *(float4*)(orow + 4) = *(const float4*)(v + 4);
    }

    #pragma unroll
    for (int o = 16; o; o >>= 1) {
        lmin = fminf(lmin, __shfl_down_sync(0xFFFFFFFFu, lmin, o));
        lmax = fmaxf(lmax, __shfl_down_sync(0xFFFFFFFFu, lmax, o));
    }
    __shared__ float smn[8], smx[8];
    int lane = tid & 31, wrp = tid >> 5;
    if (!lane) { smn[wrp] = lmin; smx[wrp] = lmax; }
    __syncthreads();
    if (tid == 0) {
        float mn = smn[0], mx = smx[0];
        #pragma unroll
        for (int i = 1; i < 8; i++) { mn = fminf(mn, smn[i]); mx = fmaxf(mx, smx[i]); }
        int cl = m0 / nPerCluster;
        atomicMin(&g_cmin[cl], f2ord(mn));
        atomicMax(&g_cmax[cl], f2ord(mx));
    }
}

// ---------------------------------------------------------------------------
__global__ void range_kernel(const float* __restrict__ act_range,
                             const int* __restrict__ cinfo,
                             float* __restrict__ rout, int Kc) {
    int t = threadIdx.x;
    if (t < 2 * Kc) rout[t] = act_range[t];
    __syncthreads();
    if (t < Kc) {
        int c = cinfo[2 * t];
        float mn = ord2f(g_cmin[t]);
        float mx = ord2f(g_cmax[t]);
        float om = act_range[2 * c], oM = act_range[2 * c + 1];
        const float SM  = 0.999f;
        const float OMS = (float)(1.0 - 0.999);   // matches JAX's (1.0 - SMOOTH) cast to f32
        float nm = om * SM + mn * OMS;
        float nM = oM * SM + mx * OMS;
        rout[2 * c]     = nm;
        rout[2 * c + 1] = nM;
        float s = __fdiv_rn(nM - nm, 255.0f);
        g_s3[t] = s;
        g_z3[t] = -rintf(__fdiv_rn(nm, s));
    }
}

// ---------------------------------------------------------------------------
__global__ void quant_out_kernel(float* __restrict__ out, long total4,
                                 int ND, int nPerCluster) {
    long stride = (long)gridDim.x * blockDim.x;
    for (long i = (long)blockIdx.x * blockDim.x + threadIdx.x; i < total4; i += stride) {
        long e = i * 4;
        int row = (int)(e / ND);
        int g = row / nPerCluster;
        float s = g_s3[g], zp = g_z3[g];
        float4 v = ((float4*)out)[i];
        v.x = (fminf(fmaxf(rintf(__fdiv_rn(v.x, s) + zp), 0.0f), 255.0f) - zp) * s;
        v.y = (fminf(fmaxf(rintf(__fdiv_rn(v.y, s) + zp), 0.0f), 255.0f) - zp) * s;
        v.z = (fminf(fmaxf(rintf(__fdiv_rn(v.z, s) + zp), 0.0f), 255.0f) - zp) * s;
        v.w = (fminf(fmaxf(rintf(__fdiv_rn(v.w, s) + zp), 0.0f), 255.0f) - zp) * s;
        ((float4*)out)[i] = v;
    }
}

// ---------------------------------------------------------------------------
extern "C" void kernel_launch(void* const* d_in, const int* in_sizes, int n_in,
                              void* d_out, int out_size) {
    const float* x         = (const float*)d_in[0];
    const float* weight    = (const float*)d_in[1];
    const float* bias      = (const float*)d_in[2];
    const float* act_range = (const float*)d_in[3];
    const int*   cinfo     = (const int*)d_in[4];

    int OUT = in_sizes[2];             // bias length
    int IN  = in_sizes[1] / OUT;       // weight is [OUT, IN]
    int B   = in_sizes[0] / IN;        // x is [B, IN]
    int Kc  = in_sizes[3] / 2;         // act_range [K, 2]
    int nPer = B / Kc;

    float* out  = (float*)d_out;
    float* rout = out + (size_t)B * OUT;

    long w4 = (long)OUT * IN / 4;
    long o4 = (long)B * OUT / 4;

    init_scratch_kernel<<<1, 64>>>();
    wminmax_kernel<<<1024, 256>>>(weight, w4);
    wparams_kernel<<<1, 1>>>();
    wquant_kernel<<<2048, 256>>>(weight, w4);

    dim3 grid(OUT / BN, B / BM);
    gemm_kernel<<<grid, NTHREADS>>>(x, bias, out, IN, OUT, nPer);

    range_kernel<<<1, 128>>>(act_range, cinfo, rout, Kc);
    quant_out_kernel<<<2048, 256>>>(out, o4, OUT, nPer);
}

// round 7
// speedup vs baseline: 1.1014x; 1.1014x over previous
#include <cuda_runtime.h>
#include <cstdint>

// ---------------------------------------------------------------------------
// PCQLinear: w_q = fakequant(weight, global min/max); out = x @ w_q^T + bias;
// per-cluster (K groups of B/K rows) min/max -> EMA range update -> fakequant.
// GEMM via warp-level mma.sync m16n8k8 tf32, 3xTF32 split (hh + hl + lh),
// fp32 accumulate. Base sm_103 target only (no tcgen05 — harness PTX target
// is sm_103 without the 'a' suffix).
// ---------------------------------------------------------------------------

#define FLT_BIG 3.402823466e38f

#define BM 128
#define BN 128
#define BK 32
#define NTH 256

// stage layout (floats): AH[2][128][16] | AL | BH | BL, each 4096 floats
#define ST_FLOATS 16384              // 64 KB per stage
#define SMEM_BYTES (2 * ST_FLOATS * 4)   // 128 KB

// Scratch (allocation-free: __device__ globals)
__device__ float g_wq[4096l * 4096];
__device__ unsigned g_wmin_u, g_wmax_u;
__device__ float g_sw, g_zw;
__device__ unsigned g_cmin[64], g_cmax[64];
__device__ float g_s3[64], g_z3[64];

// ---------------------------------------------------------------------------
__device__ __forceinline__ unsigned f2ord(float f) {
    unsigned u = __float_as_uint(f);
    return (u & 0x80000000u) ? ~u : (u | 0x80000000u);
}
__device__ __forceinline__ float ord2f(unsigned u) {
    return __uint_as_float((u & 0x80000000u) ? (u & 0x7FFFFFFFu) : ~u);
}
__device__ __forceinline__ uint32_t tf32r(float x) {
    uint32_t r;
    asm("cvt.rna.tf32.f32 %0, %1;" : "=r"(r) : "f"(x));
    return r;
}
__device__ __forceinline__ void mma8(float* d,
                                     uint32_t a0, uint32_t a1, uint32_t a2, uint32_t a3,
                                     uint32_t b0, uint32_t b1) {
    asm("mma.sync.aligned.m16n8k8.row.col.f32.tf32.tf32.f32 "
        "{%0,%1,%2,%3}, {%4,%5,%6,%7}, {%8,%9}, {%0,%1,%2,%3};"
        : "+f"(d[0]), "+f"(d[1]), "+f"(d[2]), "+f"(d[3])
        : "r"(a0), "r"(a1), "r"(a2), "r"(a3), "r"(b0), "r"(b1));
}
#define FU(x) __float_as_uint(x)

// ---------------------------------------------------------------------------
__global__ void init_scratch_kernel() {
    int t = threadIdx.x;
    if (t == 0) { g_wmin_u = 0xFFFFFFFFu; g_wmax_u = 0u; }
    if (t < 64) { g_cmin[t] = 0xFFFFFFFFu; g_cmax[t] = 0u; }
}

// ---------------------------------------------------------------------------
__global__ void wminmax_kernel(const float* __restrict__ w, long n4) {
    float mn = FLT_BIG, mx = -FLT_BIG;
    long stride = (long)gridDim.x * blockDim.x;
    for (long i = (long)blockIdx.x * blockDim.x + threadIdx.x; i < n4; i += stride) {
        float4 v = ((const float4*)w)[i];
        mn = fminf(mn, fminf(fminf(v.x, v.y), fminf(v.z, v.w)));
        mx = fmaxf(mx, fmaxf(fmaxf(v.x, v.y), fmaxf(v.z, v.w)));
    }
    #pragma unroll
    for (int o = 16; o; o >>= 1) {
        mn = fminf(mn, __shfl_down_sync(0xFFFFFFFFu, mn, o));
        mx = fmaxf(mx, __shfl_down_sync(0xFFFFFFFFu, mx, o));
    }
    __shared__ float smn[8], smx[8];
    int lane = threadIdx.x & 31, wrp = threadIdx.x >> 5;
    if (!lane) { smn[wrp] = mn; smx[wrp] = mx; }
    __syncthreads();
    if (threadIdx.x == 0) {
        for (int i = 1; i < (int)(blockDim.x >> 5); i++) {
            mn = fminf(mn, smn[i]); mx = fmaxf(mx, smx[i]);
        }
        atomicMin(&g_wmin_u, f2ord(mn));
        atomicMax(&g_wmax_u, f2ord(mx));
    }
}

__global__ void wparams_kernel() {
    float mn = ord2f(g_wmin_u), mx = ord2f(g_wmax_u);
    float s = __fdiv_rn(mx - mn, 255.0f);
    g_sw = s;
    g_zw = -rintf(__fdiv_rn(mn, s));
}

__global__ void wquant_kernel(const float* __restrict__ w, long n4) {
    float s = g_sw, zp = g_zw;
    long stride = (long)gridDim.x * blockDim.x;
    for (long i = (long)blockIdx.x * blockDim.x + threadIdx.x; i < n4; i += stride) {
        float4 v = ((const float4*)w)[i];
        v.x = (fminf(fmaxf(rintf(__fdiv_rn(v.x, s) + zp), 0.0f), 255.0f) - zp) * s;
        v.y = (fminf(fmaxf(rintf(__fdiv_rn(v.y, s) + zp), 0.0f), 255.0f) - zp) * s;
        v.z = (fminf(fmaxf(rintf(__fdiv_rn(v.z, s) + zp), 0.0f), 255.0f) - zp) * s;
        v.w = (fminf(fmaxf(rintf(__fdiv_rn(v.w, s) + zp), 0.0f), 255.0f) - zp) * s;
        ((float4*)g_wq)[i] = v;
    }
}

// ---------------------------------------------------------------------------
// mma.sync tf32 3-pass GEMM. CTA 128x128, BK=32, 8 warps (4x2), warp 32x64.
// Smem is k-permuted within 16-wide blocks: col = (k%4)*4 + k/4, XOR-swizzled
// by row&3, so every fragment load is one conflict-free LDS.128.
// ---------------------------------------------------------------------------
__global__ __launch_bounds__(NTH, 1)
void gemm_mma_kernel(const float* __restrict__ X, const float* __restrict__ bias,
                     float* __restrict__ out, int IND, int ND, int nPerCluster) {
    extern __shared__ float smf[];
    const int tid  = threadIdx.x;
    const int lane = tid & 31, wid = tid >> 5;
    const int q = lane & 3, r4 = lane >> 2;
    const int wm = wid & 3, wn = wid >> 2;      // 4 x 2 warp grid
    const int Rw = wm * 32, Cw = wn * 64;
    const int m0 = blockIdx.y * BM;
    const int n0 = blockIdx.x * BN;

    float acc[2][8][4];
    #pragma unroll
    for (int mi = 0; mi < 2; mi++)
        #pragma unroll
        for (int nj = 0; nj < 8; nj++)
            #pragma unroll
            for (int e = 0; e < 4; e++) acc[mi][nj][e] = 0.0f;

    // gmem staging regs
    float4 ga[4], gb[4];
    const int midx = tid >> 3;          // 0..127 tile row (A) / tile col (B)
    const int j4   = tid & 7;           // float4 index along k32
    const int bsel = j4 >> 2;           // k16 block
    const int jj   = j4 & 3;
    const int sw   = midx & 3;          // xor swizzle key (same every i: midx+32i keeps &3)

    auto loadG = [&](int ck) {
        const int kk = ck * BK + j4 * 4;
        #pragma unroll
        for (int i = 0; i < 4; i++) {
            int m = midx + i * 32;
            ga[i] = *(const float4*)(X    + (size_t)(m0 + m) * IND + kk);
            gb[i] = *(const float4*)(g_wq + (size_t)(n0 + m) * IND + kk);
        }
    };
    auto storeS = [&](int s) {
        float* base = smf + s * ST_FLOATS;
        const int c0 = ((0 ^ sw) << 2) + jj, c1 = ((1 ^ sw) << 2) + jj;
        const int c2 = ((2 ^ sw) << 2) + jj, c3 = ((3 ^ sw) << 2) + jj;
        #pragma unroll
        for (int i = 0; i < 4; i++) {
            int m = midx + i * 32;
            float* pH = base + bsel * 2048 + m * 16;
            float* pL = pH + 4096;
            float4 v = ga[i];
            uint32_t hx = tf32r(v.x), hy = tf32r(v.y), hz = tf32r(v.z), hw = tf32r(v.w);
            pH[c0] = __uint_as_float(hx); pH[c1] = __uint_as_float(hy);
            pH[c2] = __uint_as_float(hz); pH[c3] = __uint_as_float(hw);
            pL[c0] = __uint_as_float(tf32r(v.x - __uint_as_float(hx)));
            pL[c1] = __uint_as_float(tf32r(v.y - __uint_as_float(hy)));
            pL[c2] = __uint_as_float(tf32r(v.z - __uint_as_float(hz)));
            pL[c3] = __uint_as_float(tf32r(v.w - __uint_as_float(hw)));
            float* qH = pH + 8192;
            float* qL = pL + 8192;
            v = gb[i];
            hx = tf32r(v.x); hy = tf32r(v.y); hz = tf32r(v.z); hw = tf32r(v.w);
            qH[c0] = __uint_as_float(hx); qH[c1] = __uint_as_float(hy);
            qH[c2] = __uint_as_float(hz); qH[c3] = __uint_as_float(hw);
            qL[c0] = __uint_as_float(tf32r(v.x - __uint_as_float(hx)));
            qL[c1] = __uint_as_float(tf32r(v.y - __uint_as_float(hy)));
            qL[c2] = __uint_as_float(tf32r(v.z - __uint_as_float(hz)));
            qL[c3] = __uint_as_float(tf32r(v.w - __uint_as_float(hw)));
        }
    };

    auto compute = [&](int s) {
        const float* base = smf + s * ST_FLOATS;
        #pragma unroll
        for (int b = 0; b < 2; b++) {
            const float* AH = base + b * 2048;
            const float* BH = AH + 8192;
            float4 aH[2], aH8[2], aL[2], aL8[2];
            #pragma unroll
            for (int mi = 0; mi < 2; mi++) {
                int r0 = Rw + mi * 16 + r4;
                int r1 = r0 + 8;
                int o0 = r0 * 16 + ((q ^ (r0 & 3)) << 2);
                int o1 = r1 * 16 + ((q ^ (r1 & 3)) << 2);
                aH[mi]  = *(const float4*)(AH + o0);
                aH8[mi] = *(const float4*)(AH + o1);
                aL[mi]  = *(const float4*)(AH + 4096 + o0);
                aL8[mi] = *(const float4*)(AH + 4096 + o1);
            }
            #pragma unroll
            for (int h = 0; h < 2; h++) {
                float4 bh[4], bl[4];
                #pragma unroll
                for (int u = 0; u < 4; u++) {
                    int n = Cw + (h * 4 + u) * 8 + r4;
                    int o = n * 16 + ((q ^ (n & 3)) << 2);
                    bh[u] = *(const float4*)(BH + o);
                    bl[u] = *(const float4*)(BH + 4096 + o);
                }
                #pragma unroll
                for (int u = 0; u < 4; u++) {
                    int nj = h * 4 + u;
                    #pragma unroll
                    for (int mi = 0; mi < 2; mi++) {
                        float* d = acc[mi][nj];
                        // k-atom 0 (.x/.y), passes hh, hl, lh
                        mma8(d, FU(aH[mi].x), FU(aH8[mi].x), FU(aH[mi].y), FU(aH8[mi].y),
                                FU(bh[u].x), FU(bh[u].y));
                        mma8(d, FU(aH[mi].x), FU(aH8[mi].x), FU(aH[mi].y), FU(aH8[mi].y),
                                FU(bl[u].x), FU(bl[u].y));
                        mma8(d, FU(aL[mi].x), FU(aL8[mi].x), FU(aL[mi].y), FU(aL8[mi].y),
                                FU(bh[u].x), FU(bh[u].y));
                        // k-atom 1 (.z/.w)
                        mma8(d, FU(aH[mi].z), FU(aH8[mi].z), FU(aH[mi].w), FU(aH8[mi].w),
                                FU(bh[u].z), FU(bh[u].w));
                        mma8(d, FU(aH[mi].z), FU(aH8[mi].z), FU(aH[mi].w), FU(aH8[mi].w),
                                FU(bl[u].z), FU(bl[u].w));
                        mma8(d, FU(aL[mi].z), FU(aL8[mi].z), FU(aL[mi].w), FU(aL8[mi].w),
                                FU(bh[u].z), FU(bh[u].w));
                    }
                }
            }
        }
    };

    const int NCH = IND / BK;
    loadG(0);
    storeS(0);
    __syncthreads();

    for (int k = 0; k < NCH; k++) {
        const int s = k & 1;
        if (k + 1 < NCH) loadG(k + 1);
        compute(s);
        if (k + 1 < NCH) storeS(s ^ 1);
        __syncthreads();
    }

    // epilogue: bias + per-cluster min/max + direct stores
    float lmin = FLT_BIG, lmax = -FLT_BIG;
    float2 bz[8];
    #pragma unroll
    for (int nj = 0; nj < 8; nj++)
        bz[nj] = *(const float2*)(bias + n0 + Cw + nj * 8 + 2 * q);

    #pragma unroll
    for (int mi = 0; mi < 2; mi++) {
        int r0 = m0 + Rw + mi * 16 + r4;
        #pragma unroll
        for (int nj = 0; nj < 8; nj++) {
            int col = n0 + Cw + nj * 8 + 2 * q;
            float v0 = acc[mi][nj][0] + bz[nj].x;
            float v1 = acc[mi][nj][1] + bz[nj].y;
            float v2 = acc[mi][nj][2] + bz[nj].x;
            float v3 = acc[mi][nj][3] + bz[nj].y;
            lmin = fminf(lmin, fminf(fminf(v0, v1), fminf(v2, v3)));
            lmax = fmaxf(lmax, fmaxf(fmaxf(v0, v1), fmaxf(v2, v3)));
            *(float2*)(out + (size_t)r0 * ND + col)       = make_float2(v0, v1);
            *(float2*)(out + (size_t)(r0 + 8) * ND + col) = make_float2(v2, v3);
        }
    }

    #pragma unroll
    for (int o = 16; o; o >>= 1) {
        lmin = fminf(lmin, __shfl_down_sync(0xFFFFFFFFu, lmin, o));
        lmax = fmaxf(lmax, __shfl_down_sync(0xFFFFFFFFu, lmax, o));
    }
    __shared__ float smn[8], smx[8];
    if (!lane) { smn[wid] = lmin; smx[wid] = lmax; }
    __syncthreads();
    if (tid == 0) {
        float mn = smn[0], mx = smx[0];
        #pragma unroll
        for (int i = 1; i < 8; i++) { mn = fminf(mn, smn[i]); mx = fmaxf(mx, smx[i]); }
        int cl = m0 / nPerCluster;
        atomicMin(&g_cmin[cl], f2ord(mn));
        atomicMax(&g_cmax[cl], f2ord(mx));
    }
}

// ---------------------------------------------------------------------------
__global__ void range_kernel(const float* __restrict__ act_range,
                             const int* __restrict__ cinfo,
                             float* __restrict__ rout, int Kc) {
    int t = threadIdx.x;
    if (t < 2 * Kc) rout[t] = act_range[t];
    __syncthreads();
    if (t < Kc) {
        int c = cinfo[2 * t];
        float mn = ord2f(g_cmin[t]);
        float mx = ord2f(g_cmax[t]);
        float om = act_range[2 * c], oM = act_range[2 * c + 1];
        const float SM  = 0.999f;
        const float OMS = (float)(1.0 - 0.999);
        float nm = om * SM + mn * OMS;
        float nM = oM * SM + mx * OMS;
        rout[2 * c]     = nm;
        rout[2 * c + 1] = nM;
        float s = __fdiv_rn(nM - nm, 255.0f);
        g_s3[t] = s;
        g_z3[t] = -rintf(__fdiv_rn(nm, s));
    }
}

// ---------------------------------------------------------------------------
__global__ void quant_out_kernel(float* __restrict__ out, long total4,
                                 int ND, int nPerCluster) {
    long stride = (long)gridDim.x * blockDim.x;
    for (long i = (long)blockIdx.x * blockDim.x + threadIdx.x; i < total4; i += stride) {
        long e = i * 4;
        int row = (int)(e / ND);
        int g = row / nPerCluster;
        float s = g_s3[g], zp = g_z3[g];
        float4 v = ((float4*)out)[i];
        v.x = (fminf(fmaxf(rintf(__fdiv_rn(v.x, s) + zp), 0.0f), 255.0f) - zp) * s;
        v.y = (fminf(fmaxf(rintf(__fdiv_rn(v.y, s) + zp), 0.0f), 255.0f) - zp) * s;
        v.z = (fminf(fmaxf(rintf(__fdiv_rn(v.z, s) + zp), 0.0f), 255.0f) - zp) * s;
        v.w = (fminf(fmaxf(rintf(__fdiv_rn(v.w, s) + zp), 0.0f), 255.0f) - zp) * s;
        ((float4*)out)[i] = v;
    }
}

// ---------------------------------------------------------------------------
extern "C" void kernel_launch(void* const* d_in, const int* in_sizes, int n_in,
                              void* d_out, int out_size) {
    const float* x         = (const float*)d_in[0];
    const float* weight    = (const float*)d_in[1];
    const float* bias      = (const float*)d_in[2];
    const float* act_range = (const float*)d_in[3];
    const int*   cinfo     = (const int*)d_in[4];

    int OUT = in_sizes[2];             // bias length
    int IN  = in_sizes[1] / OUT;       // weight is [OUT, IN]
    int B   = in_sizes[0] / IN;        // x is [B, IN]
    int Kc  = in_sizes[3] / 2;         // act_range [K, 2]
    int nPer = B / Kc;

    float* out  = (float*)d_out;
    float* rout = out + (size_t)B * OUT;

    long w4 = (long)OUT * IN / 4;
    long o4 = (long)B * OUT / 4;

    init_scratch_kernel<<<1, 64>>>();
    wminmax_kernel<<<1024, 256>>>(weight, w4);
    wparams_kernel<<<1, 1>>>();
    wquant_kernel<<<2048, 256>>>(weight, w4);

    cudaFuncSetAttribute(gemm_mma_kernel,
                         cudaFuncAttributeMaxDynamicSharedMemorySize, SMEM_BYTES);
    dim3 grid(OUT / BN, B / BM);
    gemm_mma_kernel<<<grid, NTH, SMEM_BYTES>>>(x, bias, out, IN, OUT, nPer);

    range_kernel<<<1, 128>>>(act_range, cinfo, rout, Kc);
    quant_out_kernel<<<2048, 256>>>(out, o4, OUT, nPer);
}

// round 8
// speedup vs baseline: 4.3440x; 3.9440x over previous
#include <cuda_runtime.h>
#include <cuda_bf16.h>
#include <cstdint>

// ---------------------------------------------------------------------------
// PCQLinear: w_q = fakequant(weight, global min/max); out = x @ w_q^T + bias;
// per-cluster min/max -> EMA range update -> fakequant.
//
// GEMM trick: w_q = s*(q - z) with (q - z) small integers -> EXACT in bf16.
// out = s * (x @ Qc^T) + bias, Qc = q - z in bf16 (no B split needed).
// x split into bf16 hi+lo (2 passes), mma.sync m16n8k16 bf16, fp32 accum.
// ---------------------------------------------------------------------------

#define FLT_BIG 3.402823466e38f

#define BM 128
#define BN 128
#define BKB 32                 // k per chunk (bf16 elems) = 64B rows
#define NTH 256
#define STAGE_B 24576          // AH 8K | AL 8K | B 8K
#define OFF_AL 8192
#define OFF_B  16384
#define SMEM_BYTES (2 * STAGE_B)   // 48 KB

// Scratch (allocation-free: __device__ globals)
__device__ __nv_bfloat16 g_wqc[4096l * 4096];    // (q - z), exact ints in bf16
__device__ __nv_bfloat16 g_xh[10240l * 4096];
__device__ __nv_bfloat16 g_xl[10240l * 4096];
__device__ unsigned g_wmin_u, g_wmax_u;
__device__ float g_sw, g_zw;
__device__ unsigned g_cmin[64], g_cmax[64];
__device__ float g_s3[64], g_z3[64];

// ---------------------------------------------------------------------------
__device__ __forceinline__ unsigned f2ord(float f) {
    unsigned u = __float_as_uint(f);
    return (u & 0x80000000u) ? ~u : (u | 0x80000000u);
}
__device__ __forceinline__ float ord2f(unsigned u) {
    return __uint_as_float((u & 0x80000000u) ? (u & 0x7FFFFFFFu) : ~u);
}
__device__ __forceinline__ uint32_t smem_u32(const void* p) {
    uint32_t a;
    asm("{ .reg .u64 t; cvta.to.shared.u64 t, %1; cvt.u32.u64 %0, t; }"
        : "=r"(a) : "l"(p));
    return a;
}
__device__ __forceinline__ void cp16(uint32_t dst, const void* src) {
    asm volatile("cp.async.cg.shared.global [%0], [%1], 16;"
                 :: "r"(dst), "l"(src) : "memory");
}
__device__ __forceinline__ void cp_commit() {
    asm volatile("cp.async.commit_group;" ::: "memory");
}
template <int N>
__device__ __forceinline__ void cp_wait() {
    asm volatile("cp.async.wait_group %0;" :: "n"(N) : "memory");
}
__device__ __forceinline__ void ldsm4(uint32_t* r, uint32_t addr) {
    asm volatile("ldmatrix.sync.aligned.m8n8.x4.shared.b16 {%0,%1,%2,%3}, [%4];"
                 : "=r"(r[0]), "=r"(r[1]), "=r"(r[2]), "=r"(r[3]) : "r"(addr));
}
__device__ __forceinline__ void mma16(float* d, const uint32_t* a,
                                      uint32_t b0, uint32_t b1) {
    asm("mma.sync.aligned.m16n8k16.row.col.f32.bf16.bf16.f32 "
        "{%0,%1,%2,%3}, {%4,%5,%6,%7}, {%8,%9}, {%0,%1,%2,%3};"
        : "+f"(d[0]), "+f"(d[1]), "+f"(d[2]), "+f"(d[3])
        : "r"(a[0]), "r"(a[1]), "r"(a[2]), "r"(a[3]), "r"(b0), "r"(b1));
}

// ---------------------------------------------------------------------------
__global__ void init_scratch_kernel() {
    int t = threadIdx.x;
    if (t == 0) { g_wmin_u = 0xFFFFFFFFu; g_wmax_u = 0u; }
    if (t < 64) { g_cmin[t] = 0xFFFFFFFFu; g_cmax[t] = 0u; }
}

// ---------------------------------------------------------------------------
__global__ void wminmax_kernel(const float* __restrict__ w, long n4) {
    float mn = FLT_BIG, mx = -FLT_BIG;
    long stride = (long)gridDim.x * blockDim.x;
    for (long i = (long)blockIdx.x * blockDim.x + threadIdx.x; i < n4; i += stride) {
        float4 v = ((const float4*)w)[i];
        mn = fminf(mn, fminf(fminf(v.x, v.y), fminf(v.z, v.w)));
        mx = fmaxf(mx, fmaxf(fmaxf(v.x, v.y), fmaxf(v.z, v.w)));
    }
    #pragma unroll
    for (int o = 16; o; o >>= 1) {
        mn = fminf(mn, __shfl_down_sync(0xFFFFFFFFu, mn, o));
        mx = fmaxf(mx, __shfl_down_sync(0xFFFFFFFFu, mx, o));
    }
    __shared__ float smn[8], smx[8];
    int lane = threadIdx.x & 31, wrp = threadIdx.x >> 5;
    if (!lane) { smn[wrp] = mn; smx[wrp] = mx; }
    __syncthreads();
    if (threadIdx.x == 0) {
        for (int i = 1; i < (int)(blockDim.x >> 5); i++) {
            mn = fminf(mn, smn[i]); mx = fmaxf(mx, smx[i]);
        }
        atomicMin(&g_wmin_u, f2ord(mn));
        atomicMax(&g_wmax_u, f2ord(mx));
    }
}

__global__ void wparams_kernel() {
    float mn = ord2f(g_wmin_u), mx = ord2f(g_wmax_u);
    float s = __fdiv_rn(mx - mn, 255.0f);
    g_sw = s;
    g_zw = -rintf(__fdiv_rn(mn, s));
}

// quantize weights to centered integer codes Qc = clip(round(w/s+z),0,255)-z,
// stored exactly as bf16 (|Qc| <= 255).
__global__ void wquant_kernel(const float* __restrict__ w, long n4) {
    float s = g_sw, zp = g_zw;
    long stride = (long)gridDim.x * blockDim.x;
    for (long i = (long)blockIdx.x * blockDim.x + threadIdx.x; i < n4; i += stride) {
        float4 v = ((const float4*)w)[i];
        float q0 = fminf(fmaxf(rintf(__fdiv_rn(v.x, s) + zp), 0.0f), 255.0f) - zp;
        float q1 = fminf(fmaxf(rintf(__fdiv_rn(v.y, s) + zp), 0.0f), 255.0f) - zp;
        float q2 = fminf(fmaxf(rintf(__fdiv_rn(v.z, s) + zp), 0.0f), 255.0f) - zp;
        float q3 = fminf(fmaxf(rintf(__fdiv_rn(v.w, s) + zp), 0.0f), 255.0f) - zp;
        __nv_bfloat162* o = (__nv_bfloat162*)g_wqc + i * 2;
        o[0] = __nv_bfloat162(__float2bfloat16(q0), __float2bfloat16(q1));
        o[1] = __nv_bfloat162(__float2bfloat16(q2), __float2bfloat16(q3));
    }
}

// split x into bf16 hi + lo
__global__ void xsplit_kernel(const float* __restrict__ x, long n4) {
    long stride = (long)gridDim.x * blockDim.x;
    for (long i = (long)blockIdx.x * blockDim.x + threadIdx.x; i < n4; i += stride) {
        float4 v = ((const float4*)x)[i];
        __nv_bfloat16 h0 = __float2bfloat16(v.x);
        __nv_bfloat16 h1 = __float2bfloat16(v.y);
        __nv_bfloat16 h2 = __float2bfloat16(v.z);
        __nv_bfloat16 h3 = __float2bfloat16(v.w);
        __nv_bfloat162* oh = (__nv_bfloat162*)g_xh + i * 2;
        oh[0] = __nv_bfloat162(h0, h1);
        oh[1] = __nv_bfloat162(h2, h3);
        __nv_bfloat162* ol = (__nv_bfloat162*)g_xl + i * 2;
        ol[0] = __nv_bfloat162(__float2bfloat16(v.x - __bfloat162float(h0)),
                               __float2bfloat16(v.y - __bfloat162float(h1)));
        ol[1] = __nv_bfloat162(__float2bfloat16(v.z - __bfloat162float(h2)),
                               __float2bfloat16(v.w - __bfloat162float(h3)));
    }
}

// ---------------------------------------------------------------------------
// bf16 2-pass GEMM: out = s*( (xh+xl) @ Qc^T ) + bias.
// CTA 128x128, BK=32 bf16 (64B rows), cp.async double buffer, ldmatrix frags.
// smem swizzle: chunk' = chunk ^ ((row>>1)&3) -> conflict-free ldmatrix mats.
// ---------------------------------------------------------------------------
__global__ __launch_bounds__(NTH, 2)
void gemm_bf16_kernel(const float* __restrict__ bias, float* __restrict__ out,
                      int IND, int ND, int nPerCluster) {
    extern __shared__ char smc[];
    const int tid = threadIdx.x;
    const int lane = tid & 31, wid = tid >> 5;
    const int q = lane & 3, r4 = lane >> 2;
    const int wm = wid & 3, wn = wid >> 2;   // 4x2 warp grid, warp 32x64
    const int Rw = wm * 32, Cw = wn * 64;
    const int m0 = blockIdx.y * BM;
    const int n0 = blockIdx.x * BN;
    const uint32_t sb = smem_u32(smc);

    float acc[2][8][4];
    #pragma unroll
    for (int mi = 0; mi < 2; mi++)
        #pragma unroll
        for (int nb = 0; nb < 8; nb++)
            #pragma unroll
            for (int e = 0; e < 4; e++) acc[mi][nb][e] = 0.0f;

    // cp.async issue: 512 16B chunks per tensor, 2 per thread per tensor
    auto issue = [&](int ck, int s) {
        const uint32_t st = sb + s * STAGE_B;
        const long kk = (long)ck * BKB;
        #pragma unroll
        for (int i = 0; i < 2; i++) {
            int c = tid + i * 256;
            int r = c >> 2, g = c & 3;
            uint32_t d = (uint32_t)(r * 64 + ((g ^ ((r >> 1) & 3)) << 4));
            long goff = kk + g * 8;
            cp16(st + d,          g_xh  + (size_t)(m0 + r) * IND + goff);
            cp16(st + OFF_AL + d, g_xl  + (size_t)(m0 + r) * IND + goff);
            cp16(st + OFF_B + d,  g_wqc + (size_t)(n0 + r) * IND + goff);
        }
    };

    // ldmatrix offsets precomputed per lane
    // A mats: row = mbase + ((l>>3)&1)*8 + (l&7), chunk g = atom*2 + (l>>4)
    const int arow_base = (lane & 7) + ((lane >> 3) & 1) * 8;
    const int ag = lane >> 4;
    // B mats: row = nbase + (l&7), chunk g = l>>3
    const int brow_base = lane & 7;
    const int bg = lane >> 3;

    auto compute = [&](int s) {
        const uint32_t st = sb + s * STAGE_B;
        uint32_t ah[2][2][4], al[2][2][4];
        #pragma unroll
        for (int mi = 0; mi < 2; mi++)
            #pragma unroll
            for (int at = 0; at < 2; at++) {
                int r = Rw + mi * 16 + arow_base;
                int g = at * 2 + ag;
                uint32_t off = (uint32_t)(r * 64 + ((g ^ ((r >> 1) & 3)) << 4));
                ldsm4(ah[mi][at], st + off);
                ldsm4(al[mi][at], st + OFF_AL + off);
            }
        #pragma unroll
        for (int nb = 0; nb < 8; nb++) {
            int r = Cw + nb * 8 + brow_base;
            uint32_t off = (uint32_t)(r * 64 + ((bg ^ ((r >> 1) & 3)) << 4));
            uint32_t b[4];
            ldsm4(b, st + OFF_B + off);
            #pragma unroll
            for (int mi = 0; mi < 2; mi++) {
                float* d = acc[mi][nb];
                mma16(d, ah[mi][0], b[0], b[1]);
                mma16(d, al[mi][0], b[0], b[1]);
                mma16(d, ah[mi][1], b[2], b[3]);
                mma16(d, al[mi][1], b[2], b[3]);
            }
        }
    };

    const int NCH = IND / BKB;   // 128
    issue(0, 0);
    cp_commit();

    for (int k = 0; k < NCH; k++) {
        const int s = k & 1;
        if (k + 1 < NCH) {
            issue(k + 1, s ^ 1);
            cp_commit();
            cp_wait<1>();
        } else {
            cp_wait<0>();
        }
        __syncthreads();
        compute(s);
        __syncthreads();
    }

    // epilogue: scale by s, +bias, per-cluster min/max, direct stores
    const float sf = g_sw;
    float lmin = FLT_BIG, lmax = -FLT_BIG;
    float2 bz[8];
    #pragma unroll
    for (int nb = 0; nb < 8; nb++)
        bz[nb] = *(const float2*)(bias + n0 + Cw + nb * 8 + 2 * q);

    #pragma unroll
    for (int mi = 0; mi < 2; mi++) {
        int r0 = m0 + Rw + mi * 16 + r4;
        #pragma unroll
        for (int nb = 0; nb < 8; nb++) {
            int col = n0 + Cw + nb * 8 + 2 * q;
            float v0 = sf * acc[mi][nb][0] + bz[nb].x;
            float v1 = sf * acc[mi][nb][1] + bz[nb].y;
            float v2 = sf * acc[mi][nb][2] + bz[nb].x;
            float v3 = sf * acc[mi][nb][3] + bz[nb].y;
            lmin = fminf(lmin, fminf(fminf(v0, v1), fminf(v2, v3)));
            lmax = fmaxf(lmax, fmaxf(fmaxf(v0, v1), fmaxf(v2, v3)));
            *(float2*)(out + (size_t)r0 * ND + col)       = make_float2(v0, v1);
            *(float2*)(out + (size_t)(r0 + 8) * ND + col) = make_float2(v2, v3);
        }
    }

    #pragma unroll
    for (int o = 16; o; o >>= 1) {
        lmin = fminf(lmin, __shfl_down_sync(0xFFFFFFFFu, lmin, o));
        lmax = fmaxf(lmax, __shfl_down_sync(0xFFFFFFFFu, lmax, o));
    }
    __shared__ float smn[8], smx[8];
    if (!lane) { smn[wid] = lmin; smx[wid] = lmax; }
    __syncthreads();
    if (tid == 0) {
        float mn = smn[0], mx = smx[0];
        #pragma unroll
        for (int i = 1; i < 8; i++) { mn = fminf(mn, smn[i]); mx = fmaxf(mx, smx[i]); }
        int cl = m0 / nPerCluster;
        atomicMin(&g_cmin[cl], f2ord(mn));
        atomicMax(&g_cmax[cl], f2ord(mx));
    }
}

// ---------------------------------------------------------------------------
__global__ void range_kernel(const float* __restrict__ act_range,
                             const int* __restrict__ cinfo,
                             float* __restrict__ rout, int Kc) {
    int t = threadIdx.x;
    if (t < 2 * Kc) rout[t] = act_range[t];
    __syncthreads();
    if (t < Kc) {
        int c = cinfo[2 * t];
        float mn = ord2f(g_cmin[t]);
        float mx = ord2f(g_cmax[t]);
        float om = act_range[2 * c], oM = act_range[2 * c + 1];
        const float SM  = 0.999f;
        const float OMS = (float)(1.0 - 0.999);
        float nm = om * SM + mn * OMS;
        float nM = oM * SM + mx * OMS;
        rout[2 * c]     = nm;
        rout[2 * c + 1] = nM;
        float s = __fdiv_rn(nM - nm, 255.0f);
        g_s3[t] = s;
        g_z3[t] = -rintf(__fdiv_rn(nm, s));
    }
}

// ---------------------------------------------------------------------------
__global__ void quant_out_kernel(float* __restrict__ out, long total4,
                                 int ND, int nPerCluster) {
    long stride = (long)gridDim.x * blockDim.x;
    for (long i = (long)blockIdx.x * blockDim.x + threadIdx.x; i < total4; i += stride) {
        long e = i * 4;
        int row = (int)(e / ND);
        int g = row / nPerCluster;
        float s = g_s3[g], zp = g_z3[g];
        float4 v = ((float4*)out)[i];
        v.x = (fminf(fmaxf(rintf(__fdiv_rn(v.x, s) + zp), 0.0f), 255.0f) - zp) * s;
        v.y = (fminf(fmaxf(rintf(__fdiv_rn(v.y, s) + zp), 0.0f), 255.0f) - zp) * s;
        v.z = (fminf(fmaxf(rintf(__fdiv_rn(v.z, s) + zp), 0.0f), 255.0f) - zp) * s;
        v.w = (fminf(fmaxf(rintf(__fdiv_rn(v.w, s) + zp), 0.0f), 255.0f) - zp) * s;
        ((float4*)out)[i] = v;
    }
}

// ---------------------------------------------------------------------------
extern "C" void kernel_launch(void* const* d_in, const int* in_sizes, int n_in,
                              void* d_out, int out_size) {
    const float* x         = (const float*)d_in[0];
    const float* weight    = (const float*)d_in[1];
    const float* bias      = (const float*)d_in[2];
    const float* act_range = (const float*)d_in[3];
    const int*   cinfo     = (const int*)d_in[4];

    int OUT = in_sizes[2];             // bias length
    int IN  = in_sizes[1] / OUT;       // weight is [OUT, IN]
    int B   = in_sizes[0] / IN;        // x is [B, IN]
    int Kc  = in_sizes[3] / 2;         // act_range [K, 2]
    int nPer = B / Kc;

    float* out  = (float*)d_out;
    float* rout = out + (size_t)B * OUT;

    long w4 = (long)OUT * IN / 4;
    long x4 = (long)B * IN / 4;
    long o4 = (long)B * OUT / 4;

    init_scratch_kernel<<<1, 64>>>();
    wminmax_kernel<<<1024, 256>>>(weight, w4);
    wparams_kernel<<<1, 1>>>();
    wquant_kernel<<<2048, 256>>>(weight, w4);
    xsplit_kernel<<<4096, 256>>>(x, x4);

    cudaFuncSetAttribute(gemm_bf16_kernel,
                         cudaFuncAttributeMaxDynamicSharedMemorySize, SMEM_BYTES);
    dim3 grid(OUT / BN, B / BM);
    gemm_bf16_kernel<<<grid, NTH, SMEM_BYTES>>>(bias, out, IN, OUT, nPer);

    range_kernel<<<1, 128>>>(act_range, cinfo, rout, Kc);
    quant_out_kernel<<<2048, 256>>>(out, o4, OUT, nPer);
}